// round 3
// baseline (speedup 1.0000x reference)
#include <cuda_runtime.h>

// Problem constants
#define BC        20      // B*C
#define HLEN      200     // his_length
#define DK        20
#define NROWS     4000    // BC*HLEN
#define ROW_ELEMS 8000    // D_INNER(400) * DK(20)
#define CTX_ELEMS (NROWS*DK)        // 80000
#define ATTN_OFF  CTX_ELEMS

// Scratch for projected q,k,v,c  (static __device__: allocation-free)
__device__ float g_q[CTX_ELEMS];
__device__ float g_k[CTX_ELEMS];
__device__ float g_v[CTX_ELEMS];
__device__ float g_c[CTX_ELEMS];

// ---------------------------------------------------------------------------
// Kernel 1: projections.  One block per (b,c,h) row; 200 threads.
// q[r][d] = sum_n Q[r][n][d] * W[n] + b   (n=0..399, d=0..19), same for K,V.
// c[r][d] = sum_n cdd[r][n][d] * W1[n] + b1 (n=0..19).
//
// float4 linear streaming: thread t processes float4 indices t + 200*j.
// Since 4*200 % 20 == 0, element d = (4*i4 + e) % 20 is fixed per (t,e):
// each thread owns exactly 4 output dims d0..d0+3 with d0 = (4t)%20 (mult of 4),
// and all 4 lanes of a float4 share the same n = (4*i4)/20.
// ---------------------------------------------------------------------------
__global__ __launch_bounds__(200) void proj_kernel(
    const float* __restrict__ Q, const float* __restrict__ K,
    const float* __restrict__ V, const float* __restrict__ cdd,
    const float* __restrict__ W, const float* __restrict__ bp,
    const float* __restrict__ W1, const float* __restrict__ b1p)
{
    __shared__ float Ws[400];
    __shared__ float W1s[20];
    __shared__ float red[200 * 4];

    const int r = blockIdx.x;      // row 0..3999
    const int t = threadIdx.x;     // 0..199

    Ws[t]       = W[t];
    Ws[t + 200] = W[t + 200];
    if (t < 20) W1s[t] = W1[t];
    __syncthreads();

    const float bias = __ldg(bp);
    const size_t base = (size_t)r * ROW_ELEMS;

    const float* srcs[3] = { Q + base, K + base, V + base };
    float* dsts[3] = { g_q, g_k, g_v };

    #pragma unroll 1
    for (int a = 0; a < 3; a++) {
        const float4* p = (const float4*)srcs[a];
        float acc0 = 0.f, acc1 = 0.f, acc2 = 0.f, acc3 = 0.f;
        #pragma unroll
        for (int j = 0; j < 10; j++) {
            const int i4 = t + 200 * j;
            const float4 v4 = p[i4];
            const float w = Ws[(i4 * 4) / 20];     // same n for all 4 lanes
            acc0 += v4.x * w;
            acc1 += v4.y * w;
            acc2 += v4.z * w;
            acc3 += v4.w * w;
        }
        red[t * 4 + 0] = acc0;
        red[t * 4 + 1] = acc1;
        red[t * 4 + 2] = acc2;
        red[t * 4 + 3] = acc3;
        __syncthreads();
        if (t < 20) {
            // output dim d = t: contributions from threads tp with tp%5 == d/4,
            // accumulator slot e = d%4.
            const int e  = t & 3;
            const int st = t >> 2;
            float s = bias;
            #pragma unroll 8
            for (int tp = st; tp < 200; tp += 5)
                s += red[tp * 4 + e];
            dsts[a][r * DK + t] = s;
        }
        __syncthreads();
    }

    // cdd projection: 20x20 per row, thread d does the 20-term reduction.
    if (t < 20) {
        const float b1 = __ldg(b1p);
        const float* cb = cdd + (size_t)r * 400;
        float s = b1;
        #pragma unroll
        for (int n = 0; n < 20; n++)
            s += cb[n * 20 + t] * W1s[n];
        g_c[r * DK + t] = s;
    }
}

// ---------------------------------------------------------------------------
// Kernel 2: attention.  grid = (bc=20, htile=8); each block handles 25 h rows.
// 256 threads: warp = one g-segment of 25 (8 segments), lane = local h (<25).
// All k/c/v reads in the g loop are warp-uniform -> broadcast, L1-resident.
// exp values live in registers (fully unrolled).  Segment sums and context
// partials are combined via shared memory.
// ---------------------------------------------------------------------------
__global__ __launch_bounds__(256) void attn_kernel(float* __restrict__ out)
{
    const int bc  = blockIdx.x;       // 0..19
    const int ht  = blockIdx.y;       // 0..7 (25 h each)
    const int t   = threadIdx.x;      // 0..255
    const int seg = t >> 5;           // 0..7  (g range [seg*25, seg*25+25))
    const int lane = t & 31;          // local h (active if < 25)

    __shared__ float sums[8][32];
    __shared__ float ctxred[8][25][20];

    const float inv_sqrt_dk = 0.22360679774997896f;   // 1/sqrt(20)
    const bool active = (lane < 25);
    const int h = ht * 25 + lane;
    const int r = bc * HLEN + h;

    float qr[20], kr[20], e[25];
    float psum = 0.f;

    if (active) {
        #pragma unroll
        for (int d = 0; d < 20; d++) {
            qr[d] = g_q[r * DK + d];
            kr[d] = g_k[r * DK + d];
        }
        #pragma unroll
        for (int j = 0; j < 25; j++) {
            const int rg = bc * HLEN + seg * 25 + j;
            float s = 0.f;
            #pragma unroll
            for (int d = 0; d < 20; d++)
                s += qr[d] * g_k[rg * DK + d] + kr[d] * g_c[rg * DK + d];
            const float ee = __expf(s * inv_sqrt_dk);
            e[j] = ee;
            psum += ee;
        }
    }
    sums[seg][lane] = psum;           // inactive lanes contribute 0
    __syncthreads();

    float tot = 1e-8f;
    #pragma unroll
    for (int sg = 0; sg < 8; sg++)
        tot += sums[sg][lane];
    const float rs = 1.f / tot;

    float ctx[20];
    #pragma unroll
    for (int d = 0; d < 20; d++) ctx[d] = 0.f;

    if (active) {
        float* attn = out + ATTN_OFF;
        #pragma unroll
        for (int j = 0; j < 25; j++) {
            const int g  = seg * 25 + j;
            const int rg = bc * HLEN + g;
            const float a = e[j] * rs;
            attn[(size_t)r * HLEN + g] = a;
            #pragma unroll
            for (int d = 0; d < 20; d++)
                ctx[d] += a * g_v[rg * DK + d];
        }
        #pragma unroll
        for (int d = 0; d < 20; d++)
            ctxred[seg][lane][d] = ctx[d];
    }
    __syncthreads();

    // Reduce context across the 8 segments; coalesced write.
    for (int idx = t; idx < 25 * 20; idx += 256) {
        const int hh = idx / 20;
        const int d  = idx - hh * 20;
        float s = 0.f;
        #pragma unroll
        for (int sg = 0; sg < 8; sg++)
            s += ctxred[sg][hh][d];
        out[(bc * HLEN + ht * 25 + hh) * DK + d] = s;
    }
}

extern "C" void kernel_launch(void* const* d_in, const int* in_sizes, int n_in,
                              void* d_out, int out_size)
{
    const float* Q   = (const float*)d_in[0];
    const float* K   = (const float*)d_in[1];
    const float* V   = (const float*)d_in[2];
    const float* cdd = (const float*)d_in[3];
    const float* W   = (const float*)d_in[4];
    const float* b   = (const float*)d_in[5];
    const float* W1  = (const float*)d_in[6];
    const float* b1  = (const float*)d_in[7];

    proj_kernel<<<NROWS, 200>>>(Q, K, V, cdd, W, b, W1, b1);
    attn_kernel<<<dim3(BC, 8), 256>>>((float*)d_out);
}

// round 4
// speedup vs baseline: 1.3648x; 1.3648x over previous
#include <cuda_runtime.h>

// Problem constants
#define BC        20      // B*C
#define HLEN      200     // his_length
#define DK        20
#define NROWS     4000    // BC*HLEN
#define ROW_ELEMS 8000    // D_INNER(400) * DK(20)
#define CTX_ELEMS (NROWS*DK)        // 80000
#define ATTN_OFF  CTX_ELEMS

// Scratch for projected q,k,v,c  (static __device__: allocation-free)
__device__ float g_q[CTX_ELEMS];
__device__ float g_k[CTX_ELEMS];
__device__ float g_v[CTX_ELEMS];
__device__ float g_c[CTX_ELEMS];

// ---------------------------------------------------------------------------
// Kernel 1: projections.  grid = (row 0..3999, tensor 0..2); 200 threads.
// q[r][d] = sum_n X[r][n][d] * W[n] + b   (n=0..399, d=0..19).
// c[r][d] = sum_n cdd[r][n][d] * W1[n] + b1 (n=0..19)  — folded into a==2.
//
// float4 linear streaming: thread t processes float4 indices t + 200*j.
// Since 4*200 % 20 == 0, element d = (4t + e) % 20 is fixed per (t,e):
// all 4 lanes of a float4 share the same weight index n = (4*i4)/20.
// ---------------------------------------------------------------------------
__global__ __launch_bounds__(200) void proj_kernel(
    const float* __restrict__ Q, const float* __restrict__ K,
    const float* __restrict__ V, const float* __restrict__ cdd,
    const float* __restrict__ W, const float* __restrict__ bp,
    const float* __restrict__ W1, const float* __restrict__ b1p)
{
    __shared__ float Ws[400];
    __shared__ float red[200 * 4];

    const int r = blockIdx.x;      // row 0..3999
    const int a = blockIdx.y;      // tensor 0..2
    const int t = threadIdx.x;     // 0..199

    Ws[t]       = W[t];
    Ws[t + 200] = W[t + 200];
    __syncthreads();

    const float bias = __ldg(bp);
    const size_t base = (size_t)r * ROW_ELEMS;

    const float* src = (a == 0) ? (Q + base) : (a == 1) ? (K + base) : (V + base);
    float*       dst = (a == 0) ? g_q : (a == 1) ? g_k : g_v;

    const float4* p = (const float4*)src;
    float acc0 = 0.f, acc1 = 0.f, acc2 = 0.f, acc3 = 0.f;
    #pragma unroll
    for (int j = 0; j < 10; j++) {
        const int i4 = t + 200 * j;
        const float4 v4 = p[i4];
        const float w = Ws[(i4 * 4) / 20];     // same n for all 4 lanes
        acc0 += v4.x * w;
        acc1 += v4.y * w;
        acc2 += v4.z * w;
        acc3 += v4.w * w;
    }
    red[t * 4 + 0] = acc0;
    red[t * 4 + 1] = acc1;
    red[t * 4 + 2] = acc2;
    red[t * 4 + 3] = acc3;
    __syncthreads();

    if (t < 20) {
        // output dim d = t: contributions from threads tp with tp%5 == d/4,
        // accumulator slot e = d%4.
        const int e  = t & 3;
        const int st = t >> 2;
        float s = bias;
        #pragma unroll 8
        for (int tp = st; tp < 200; tp += 5)
            s += red[tp * 4 + e];
        dst[r * DK + t] = s;
    }

    // cdd projection: 20x20 per row, thread d does the 20-term reduction.
    if (a == 2 && t < 20) {
        const float b1 = __ldg(b1p);
        const float* cb = cdd + (size_t)r * 400;
        float s = b1;
        #pragma unroll
        for (int n = 0; n < 20; n++)
            s += cb[n * 20 + t] * __ldg(W1 + n);
        g_c[r * DK + t] = s;
    }
}

// ---------------------------------------------------------------------------
// Kernel 2: attention.  grid = (bc=20, ht=25); block = 256 threads = 8 warps.
// Warp w owns output row h = ht*8 + w; lanes split the g-axis: lane l covers
// g = 7*l + j (j<7, g<200) -> conflict-free shared reads (gcd(7,32)=1).
// k/c/v tiles for this bc are staged transposed into shared ([d][g], stride
// 201).  Softmax denom + 20 context dims reduced with warp shuffles.
// ---------------------------------------------------------------------------
#define SSTR 201
__global__ __launch_bounds__(256) void attn_kernel(float* __restrict__ out)
{
    __shared__ float kt[DK * SSTR];
    __shared__ float ct[DK * SSTR];
    __shared__ float vt[DK * SSTR];

    const int bc   = blockIdx.x;       // 0..19
    const int ht   = blockIdx.y;       // 0..24
    const int t    = threadIdx.x;      // 0..255
    const int w    = t >> 5;           // warp 0..7
    const int lane = t & 31;

    // Stage k, c, v for this bc (transposed): coalesced global reads.
    const int tb = bc * HLEN * DK;     // 4000-element tile base
    for (int idx = t; idx < HLEN * DK; idx += 256) {
        const int g = idx / DK;
        const int d = idx - g * DK;
        kt[d * SSTR + g] = g_k[tb + idx];
        ct[d * SSTR + g] = g_c[tb + idx];
        vt[d * SSTR + g] = g_v[tb + idx];
    }
    __syncthreads();

    const float inv_sqrt_dk = 0.22360679774997896f;   // 1/sqrt(20)
    const int h = ht * 8 + w;                         // 0..199
    const int r = bc * HLEN + h;

    // q[h], k[h] — warp-uniform
    float qr[DK], kr[DK];
    #pragma unroll
    for (int d = 0; d < DK; d++) {
        qr[d] = g_q[r * DK + d];
        kr[d] = kt[d * SSTR + h];
    }

    const int g0 = lane * 7;
    float e[7];
    float psum = 0.f;
    #pragma unroll
    for (int j = 0; j < 7; j++) {
        const int g = g0 + j;
        if (g < HLEN) {
            float s = 0.f;
            #pragma unroll
            for (int d = 0; d < DK; d++)
                s += qr[d] * kt[d * SSTR + g] + kr[d] * ct[d * SSTR + g];
            e[j] = __expf(s * inv_sqrt_dk);
            psum += e[j];
        } else {
            e[j] = 0.f;
        }
    }

    // denominator: butterfly reduce across the warp
    #pragma unroll
    for (int o = 16; o; o >>= 1)
        psum += __shfl_xor_sync(0xFFFFFFFFu, psum, o);
    const float rs = 1.f / (psum + 1e-8f);

    // attention weights out + context accumulation
    float ctx[DK];
    #pragma unroll
    for (int d = 0; d < DK; d++) ctx[d] = 0.f;

    float* attn = out + ATTN_OFF + (size_t)r * HLEN;
    #pragma unroll
    for (int j = 0; j < 7; j++) {
        const int g = g0 + j;
        if (g < HLEN) {
            const float a = e[j] * rs;
            attn[g] = a;
            #pragma unroll
            for (int d = 0; d < DK; d++)
                ctx[d] += a * vt[d * SSTR + g];
        }
    }

    // reduce each context dim across the warp; lane d keeps dim d
    float myout = 0.f;
    #pragma unroll
    for (int d = 0; d < DK; d++) {
        float v = ctx[d];
        #pragma unroll
        for (int o = 16; o; o >>= 1)
            v += __shfl_xor_sync(0xFFFFFFFFu, v, o);
        if (lane == d) myout = v;
    }
    if (lane < DK)
        out[r * DK + lane] = myout;
}

extern "C" void kernel_launch(void* const* d_in, const int* in_sizes, int n_in,
                              void* d_out, int out_size)
{
    const float* Q   = (const float*)d_in[0];
    const float* K   = (const float*)d_in[1];
    const float* V   = (const float*)d_in[2];
    const float* cdd = (const float*)d_in[3];
    const float* W   = (const float*)d_in[4];
    const float* b   = (const float*)d_in[5];
    const float* W1  = (const float*)d_in[6];
    const float* b1  = (const float*)d_in[7];

    proj_kernel<<<dim3(NROWS, 3), 200>>>(Q, K, V, cdd, W, b, W1, b1);
    attn_kernel<<<dim3(BC, 25), 256>>>((float*)d_out);
}

// round 5
// speedup vs baseline: 1.3996x; 1.0255x over previous
#include <cuda_runtime.h>

// Problem constants
#define BC        20      // B*C
#define HLEN      200     // his_length
#define DK        20
#define NROWS     4000    // BC*HLEN
#define ROW_ELEMS 8000    // D_INNER(400) * DK(20)
#define CTX_ELEMS (NROWS*DK)        // 80000
#define ATTN_OFF  CTX_ELEMS

// Projected q,k,v,c in TRANSPOSED layout: [bc][d][h] -> (bc*20+d)*200+h
__device__ float g_qT[CTX_ELEMS];
__device__ float g_kT[CTX_ELEMS];
__device__ float g_vT[CTX_ELEMS];
__device__ float g_cT[CTX_ELEMS];

// ---------------------------------------------------------------------------
// Kernel 1: projections.  grid = (row 0..3999, tensor 0..2); 200 threads.
// q[r][d] = sum_n X[r][n][d] * W[n] + b   (n=0..399, d=0..19).
// c[r][d] = sum_n cdd[r][n][d] * W1[n] + b1 — folded into a==2.
// Outputs written TRANSPOSED per bc so downstream kernels read coalesced.
// ---------------------------------------------------------------------------
__global__ __launch_bounds__(200) void proj_kernel(
    const float* __restrict__ Q, const float* __restrict__ K,
    const float* __restrict__ V, const float* __restrict__ cdd,
    const float* __restrict__ W, const float* __restrict__ bp,
    const float* __restrict__ W1, const float* __restrict__ b1p)
{
    __shared__ float Ws[400];
    __shared__ float red[200 * 4];

    const int r = blockIdx.x;      // row 0..3999
    const int a = blockIdx.y;      // tensor 0..2
    const int t = threadIdx.x;     // 0..199
    const int bc = r / HLEN;
    const int h  = r - bc * HLEN;

    Ws[t]       = W[t];
    Ws[t + 200] = W[t + 200];
    __syncthreads();

    const float bias = __ldg(bp);
    const size_t base = (size_t)r * ROW_ELEMS;

    const float* src = (a == 0) ? (Q + base) : (a == 1) ? (K + base) : (V + base);
    float*       dst = (a == 0) ? g_qT : (a == 1) ? g_kT : g_vT;

    const float4* p = (const float4*)src;
    float acc0 = 0.f, acc1 = 0.f, acc2 = 0.f, acc3 = 0.f;
    #pragma unroll
    for (int j = 0; j < 10; j++) {
        const int i4 = t + 200 * j;
        const float4 v4 = p[i4];
        const float w = Ws[(i4 * 4) / 20];     // same n for all 4 lanes
        acc0 += v4.x * w;
        acc1 += v4.y * w;
        acc2 += v4.z * w;
        acc3 += v4.w * w;
    }
    red[t * 4 + 0] = acc0;
    red[t * 4 + 1] = acc1;
    red[t * 4 + 2] = acc2;
    red[t * 4 + 3] = acc3;
    __syncthreads();

    if (t < 20) {
        // output dim d = t: contributions from threads tp with tp%5 == d/4,
        // accumulator slot e = d%4.
        const int e  = t & 3;
        const int st = t >> 2;
        float s = bias;
        #pragma unroll 8
        for (int tp = st; tp < 200; tp += 5)
            s += red[tp * 4 + e];
        dst[(bc * DK + t) * HLEN + h] = s;
    }

    // cdd projection: 20x20 per row, thread d does the 20-term reduction.
    if (a == 2 && t < 20) {
        const float b1 = __ldg(b1p);
        const float* cb = cdd + (size_t)r * 400;
        float s = b1;
        #pragma unroll
        for (int n = 0; n < 20; n++)
            s += cb[n * 20 + t] * __ldg(W1 + n);
        g_cT[(bc * DK + t) * HLEN + h] = s;
    }
}

// ---------------------------------------------------------------------------
// Kernel 2: scores.  S = [q|k] . [k|c]^T per bc  (200x200x40 GEMM),
// then E = exp(S/sqrt(dk)) written UNNORMALIZED into the attn output slot.
// Tiles 64x64, 256 threads (16x16), 4x4 register tile per thread, K=40 staged.
// ---------------------------------------------------------------------------
__global__ __launch_bounds__(256) void score_kernel(float* __restrict__ out)
{
    __shared__ float xs[40 * 64];   // xs[d][m]
    __shared__ float ys[40 * 64];   // ys[d][n]

    const int bc = blockIdx.x;
    const int m0 = blockIdx.y * 64;
    const int n0 = blockIdx.z * 64;
    const int t  = threadIdx.x;

    // Stage: coalesced LDG (transposed layout), conflict-free STS.
    for (int i = t; i < 40 * 64; i += 256) {
        const int dd = i >> 6;        // 0..39
        const int m  = i & 63;
        const int hm = m0 + m;
        const int hn = n0 + m;
        float xv = 0.f, yv = 0.f;
        if (dd < 20) {
            const int rowb = (bc * DK + dd) * HLEN;
            if (hm < HLEN) xv = g_qT[rowb + hm];
            if (hn < HLEN) yv = g_kT[rowb + hn];
        } else {
            const int rowb = (bc * DK + dd - 20) * HLEN;
            if (hm < HLEN) xv = g_kT[rowb + hm];
            if (hn < HLEN) yv = g_cT[rowb + hn];
        }
        xs[i] = xv;
        ys[i] = yv;
    }
    __syncthreads();

    const int tx = t & 15;           // n-subtile
    const int ty = t >> 4;           // m-subtile
    float acc[4][4];
    #pragma unroll
    for (int i = 0; i < 4; i++)
        #pragma unroll
        for (int j = 0; j < 4; j++)
            acc[i][j] = 0.f;

    #pragma unroll
    for (int d = 0; d < 40; d++) {
        const float4 xv = *(const float4*)&xs[d * 64 + ty * 4];
        const float4 yv = *(const float4*)&ys[d * 64 + tx * 4];
        const float xa[4] = { xv.x, xv.y, xv.z, xv.w };
        const float ya[4] = { yv.x, yv.y, yv.z, yv.w };
        #pragma unroll
        for (int i = 0; i < 4; i++)
            #pragma unroll
            for (int j = 0; j < 4; j++)
                acc[i][j] += xa[i] * ya[j];
    }

    const float inv_sqrt_dk = 0.22360679774997896f;   // 1/sqrt(20)
    float* E = out + ATTN_OFF;
    #pragma unroll
    for (int i = 0; i < 4; i++) {
        const int m = m0 + ty * 4 + i;
        if (m >= HLEN) continue;
        const int rb = (bc * HLEN + m) * HLEN;
        #pragma unroll
        for (int j = 0; j < 4; j++) {
            const int n = n0 + tx * 4 + j;
            if (n < HLEN)
                E[rb + n] = __expf(acc[i][j] * inv_sqrt_dk);
        }
    }
}

// ---------------------------------------------------------------------------
// Kernel 3: finalize.  grid (bc=20, ht=25); warp per output row h.
// Reads its E row coalesced (L2-hot), warp-butterfly row-sum, normalizes
// attn in place, accumulates context from the shared v tile.
// ---------------------------------------------------------------------------
#define VSTR 201
__global__ __launch_bounds__(256) void finalize_kernel(float* __restrict__ out)
{
    __shared__ float vt[DK * VSTR];   // vt[d][g]

    const int bc   = blockIdx.x;
    const int ht   = blockIdx.y;      // 0..24
    const int t    = threadIdx.x;
    const int w    = t >> 5;          // warp 0..7
    const int lane = t & 31;

    // Stage v (already transposed in gmem): fully coalesced, conflict-free.
    if (t < HLEN) {
        #pragma unroll
        for (int d = 0; d < DK; d++)
            vt[d * VSTR + t] = g_vT[(bc * DK + d) * HLEN + t];
    }
    __syncthreads();

    const int h = ht * 8 + w;                  // 0..199
    const int r = bc * HLEN + h;
    float* E = out + ATTN_OFF + (size_t)r * HLEN;

    // Load E row (coalesced), partial sum.
    float e[7];
    float ps = 0.f;
    #pragma unroll
    for (int k = 0; k < 7; k++) {
        const int g = lane + 32 * k;
        e[k] = (g < HLEN) ? E[g] : 0.f;
        ps += e[k];
    }
    #pragma unroll
    for (int o = 16; o; o >>= 1)
        ps += __shfl_xor_sync(0xFFFFFFFFu, ps, o);
    const float rs = 1.f / (ps + 1e-8f);

    // Normalize in place + context accumulation.
    float ctx[DK];
    #pragma unroll
    for (int d = 0; d < DK; d++) ctx[d] = 0.f;

    #pragma unroll
    for (int k = 0; k < 7; k++) {
        const int g = lane + 32 * k;
        if (g < HLEN) {
            const float a = e[k] * rs;
            E[g] = a;
            #pragma unroll
            for (int d = 0; d < DK; d++)
                ctx[d] += a * vt[d * VSTR + g];
        }
    }

    // Reduce each context dim across the warp; lane d keeps dim d.
    float myout = 0.f;
    #pragma unroll
    for (int d = 0; d < DK; d++) {
        float v = ctx[d];
        #pragma unroll
        for (int o = 16; o; o >>= 1)
            v += __shfl_xor_sync(0xFFFFFFFFu, v, o);
        if (lane == d) myout = v;
    }
    if (lane < DK)
        out[r * DK + lane] = myout;
}

extern "C" void kernel_launch(void* const* d_in, const int* in_sizes, int n_in,
                              void* d_out, int out_size)
{
    const float* Q   = (const float*)d_in[0];
    const float* K   = (const float*)d_in[1];
    const float* V   = (const float*)d_in[2];
    const float* cdd = (const float*)d_in[3];
    const float* W   = (const float*)d_in[4];
    const float* b   = (const float*)d_in[5];
    const float* W1  = (const float*)d_in[6];
    const float* b1  = (const float*)d_in[7];

    proj_kernel<<<dim3(NROWS, 3), 200>>>(Q, K, V, cdd, W, b, W1, b1);
    score_kernel<<<dim3(BC, 4, 4), 256>>>((float*)d_out);
    finalize_kernel<<<dim3(BC, 25), 256>>>((float*)d_out);
}